// round 9
// baseline (speedup 1.0000x reference)
#include <cuda_runtime.h>
#include <cuda_bf16.h>

#define NN 4096
#define MM 512
#define DD 32
#define NBLK 128        // 32 rows per block, one row per warp
#define NT   1024       // 32 warps

typedef unsigned long long ull;

// sm_103a packed fp32 FMA (FFMA2). Element 0 = low 32 bits.
__device__ __forceinline__ ull ffma2(ull a, ull b, ull c) {
    ull d;
    asm("fma.rn.f32x2 %0, %1, %2, %3;" : "=l"(d) : "l"(a), "l"(b), "l"(c));
    return d;
}
__device__ __forceinline__ ull fdup(float v) {
    unsigned u = __float_as_uint(v);
    return ((ull)u << 32) | (ull)u;
}
__device__ __forceinline__ float flo(ull v) { return __uint_as_float((unsigned)v); }
__device__ __forceinline__ float fhi(ull v) { return __uint_as_float((unsigned)(v >> 32)); }
__device__ __forceinline__ float sqrt_approx(float v) {
    float r;
    asm("sqrt.approx.f32 %0, %1;" : "=f"(r) : "f"(v));
    return r;
}

// ---- smem layout -----------------------------------------------------------
#define YT_STRIDE 516                           // floats per d-row (pad: 4-way STS, cf LDS)
#define YT_OFF    0                             // yT [32][516] floats      66048 B
#define YN2_OFF   (32 * YT_STRIDE)              // |y|^2 [512]               2048 B
#define XN2_OFF   (YN2_OFF + 512)               // |x|^2 [32]                 128 B
#define PART_OFF  (XN2_OFF + 32)                // partials [3][32]           384 B
#define XD_OFF    (PART_OFF + 96)               // xdup [32][32] ull (8B)    8192 B  (8B aligned: offset mult of 2 floats)
#define SMEM_FLOATS (XD_OFF + 32 * 32 * 2)
#define SMEM_BYTES  (SMEM_FLOATS * 4)

// ---------------------------------------------------------------------------
// Single fused kernel. warp = row n (32 rows/block), lane = m-set {4l+128j}.
//  r: 4 coalesced LDG.128 per warp straight into registers (no smem, no
//     barrier), issued first for maximum latency overlap.
//  y: staged transposed yT[d][m] (+|y|^2 via 8-lane shfl); x: pre-duplicated
//     ull table xdup[n][d] (+|x|^2). One barrier total before the mainloop.
//  dot packed over m: per d = 1 broadcast LDS.64 + 4 cf LDS.128 + 8 FFMA2.
//  C = sqrt(|x|^2+|y|^2-2dot); K = exp2(-C/(2 ln2)); R/S/T warp-reduced;
//  warp 0 runs the scalar u-recurrence with block-local early stop.
// ---------------------------------------------------------------------------
__global__ __launch_bounds__(NT) void sinkhorn_fused_kernel(
    const float* __restrict__ x,   // [NN, DD]
    const float* __restrict__ y,   // [MM, DD]
    const float* __restrict__ r,   // [NN, MM]
    float* __restrict__ out)       // [NN]
{
    extern __shared__ float sm[];
    float* yT   = sm + YT_OFF;
    float* yn2  = sm + YN2_OFF;
    float* xn2s = sm + XN2_OFF;
    float* part = sm + PART_OFF;
    ull*   xdup = (ull*)(sm + XD_OFF);

    const int tid  = threadIdx.x;
    const int warp = tid >> 5;
    const int lane = tid & 31;
    const int nb   = blockIdx.x << 5;

    // ---- r first: this warp's row, 4 coalesced LDG.128 into registers ------
    const float4* rg4 = (const float4*)(r + (size_t)(nb + warp) * MM);
    float4 rv4[4];
#pragma unroll
    for (int j = 0; j < 4; j++) rv4[j] = rg4[lane + 32 * j];   // m = 4*lane + 128*j

    // ---- y staging: coalesced read, transposed store + |y|^2 ---------------
    const float4* yg4 = (const float4*)y;       // 4096 float4
#pragma unroll
    for (int k = 0; k < 4; k++) {
        int idx  = tid + 1024 * k;
        float4 a = yg4[idx];
        int m    = idx >> 3;
        int slot = idx & 7;                      // d-quad 4*slot..4*slot+3
        yT[(4 * slot + 0) * YT_STRIDE + m] = a.x;
        yT[(4 * slot + 1) * YT_STRIDE + m] = a.y;
        yT[(4 * slot + 2) * YT_STRIDE + m] = a.z;
        yT[(4 * slot + 3) * YT_STRIDE + m] = a.w;
        float sq = fmaf(a.x, a.x, fmaf(a.y, a.y, fmaf(a.z, a.z, a.w * a.w)));
        sq += __shfl_xor_sync(0xffffffffu, sq, 1);
        sq += __shfl_xor_sync(0xffffffffu, sq, 2);
        sq += __shfl_xor_sync(0xffffffffu, sq, 4);
        if (slot == 0) yn2[m] = sq;
    }

    // ---- x staging (tid<256): pre-duplicated ull table + |x|^2 -------------
    if (tid < 256) {
        int m    = tid >> 3;                     // local row 0..31
        int slot = tid & 7;
        float4 a = ((const float4*)x)[(nb + m) * 8 + slot];
        xdup[m * 32 + 4 * slot + 0] = fdup(a.x);
        xdup[m * 32 + 4 * slot + 1] = fdup(a.y);
        xdup[m * 32 + 4 * slot + 2] = fdup(a.z);
        xdup[m * 32 + 4 * slot + 3] = fdup(a.w);
        float sq = fmaf(a.x, a.x, fmaf(a.y, a.y, fmaf(a.z, a.z, a.w * a.w)));
        sq += __shfl_xor_sync(0xffffffffu, sq, 1);
        sq += __shfl_xor_sync(0xffffffffu, sq, 2);
        sq += __shfl_xor_sync(0xffffffffu, sq, 4);
        if (slot == 0) xn2s[m] = sq;
    }
    __syncthreads();

    // ---- mainloop: 16 dots per thread, packed over m ------------------------
    const ull* xd = xdup + warp * 32;            // this row's duplicated x
    ull A[8] = {0, 0, 0, 0, 0, 0, 0, 0};         // A[2j],A[2j+1] = m-quad 4l+128j
#pragma unroll
    for (int d = 0; d < DD; d++) {
        ull xp = xd[d];                          // broadcast LDS.64
        const float* yrow = yT + d * YT_STRIDE + 4 * lane;
#pragma unroll
        for (int j = 0; j < 4; j++) {
            ulonglong2 yq = *(const ulonglong2*)(yrow + 128 * j);  // cf LDS.128
            A[2 * j]     = ffma2(xp, yq.x, A[2 * j]);
            A[2 * j + 1] = ffma2(xp, yq.y, A[2 * j + 1]);
        }
    }

    // ---- epilogue: 16 m-values per thread ----------------------------------
    const float xn2 = xn2s[warp];
    float Racc = 0.f, Sacc = 0.f, Tacc = 0.f;
#pragma unroll
    for (int j = 0; j < 4; j++) {
        const int m0 = 4 * lane + 128 * j;
        float dots[4] = { flo(A[2 * j]), fhi(A[2 * j]),
                          flo(A[2 * j + 1]), fhi(A[2 * j + 1]) };
        float4 yn = *(const float4*)(yn2 + m0);  // cf LDS.128
        float rr[4] = { rv4[j].x, rv4[j].y, rv4[j].z, rv4[j].w };
#pragma unroll
        for (int i = 0; i < 4; i++) {
            float d2 = fmaf(-2.f, dots[i], xn2 + ((const float*)&yn)[i]);
            float C  = sqrt_approx(fmaxf(d2, 0.f));
            float K  = exp2f(C * -0.72134752f);  // exp(-C/2)
            Racc += K;
            float Kr = K * rr[i];
            Sacc += Kr;
            Tacc = fmaf(Kr, C, Tacc);
        }
    }

    // ---- warp reduction -> per-row R,S,T -----------------------------------
#pragma unroll
    for (int off = 16; off > 0; off >>= 1) {
        Racc += __shfl_xor_sync(0xffffffffu, Racc, off);
        Sacc += __shfl_xor_sync(0xffffffffu, Sacc, off);
        Tacc += __shfl_xor_sync(0xffffffffu, Tacc, off);
    }
    if (lane == 0) {
        part[0 * 32 + warp] = Racc;
        part[1 * 32 + warp] = Sacc;
        part[2 * 32 + warp] = Tacc;
    }
    __syncthreads();

    if (warp == 0) {
        float R = part[0 * 32 + lane];
        float S = part[1 * 32 + lane];
        float T = part[2 * 32 + lane];

        // Scalar Sinkhorn recurrence, block-local early stop:
        //   iter 1:   u = 1/(R + 1e-8)
        //   iter t>1: u = 1/(S/(u+1e-8) + 1e-8)
        //   stop once mean_32 |u_new - u| < 0.1 (after applying update)
        float u = 1.f;
        bool done = false;
        for (int t = 0; t < 100 && !done; t++) {
            float denom = (t == 0) ? R : (S / (u + 1e-8f));
            float un = 1.f / (denom + 1e-8f);
            float e = fabsf(un - u);
            u = un;
#pragma unroll
            for (int off = 16; off > 0; off >>= 1)
                e += __shfl_xor_sync(0xffffffffu, e, off);
            done = (e < 0.1f * 32.f);            // uniform across warp
        }
        out[nb + lane] = u * T / (u + 1e-8f);
    }
}

extern "C" void kernel_launch(void* const* d_in, const int* in_sizes, int n_in,
                              void* d_out, int out_size)
{
    const float* x = (const float*)d_in[0];  // [4096, 32]
    const float* y = (const float*)d_in[1];  // [512, 32]
    const float* r = (const float*)d_in[2];  // [4096, 512]
    float* out = (float*)d_out;              // [4096]

    cudaFuncSetAttribute(sinkhorn_fused_kernel,
                         cudaFuncAttributeMaxDynamicSharedMemorySize, SMEM_BYTES);
    sinkhorn_fused_kernel<<<NBLK, NT, SMEM_BYTES>>>(x, y, r, out);
}

// round 10
// speedup vs baseline: 1.4324x; 1.4324x over previous
#include <cuda_runtime.h>
#include <cuda_bf16.h>

#define NN 4096
#define MM 512
#define DD 32
#define NBLK 128        // 32 rows per block
#define NT   1024       // 32 warps; each warp owns 16 m-columns x 32 rows

typedef unsigned long long ull;

// sm_103a packed fp32 FMA (FFMA2). Element 0 = low 32 bits.
__device__ __forceinline__ ull ffma2(ull a, ull b, ull c) {
    ull d;
    asm("fma.rn.f32x2 %0, %1, %2, %3;" : "=l"(d) : "l"(a), "l"(b), "l"(c));
    return d;
}
__device__ __forceinline__ float flo(ull v) { return __uint_as_float((unsigned)v); }
__device__ __forceinline__ float fhi(ull v) { return __uint_as_float((unsigned)(v >> 32)); }
__device__ __forceinline__ float sqrt_approx(float v) {
    float r;
    asm("sqrt.approx.f32 %0, %1;" : "=f"(r) : "f"(v));
    return r;
}
__device__ __forceinline__ void cp_async16(unsigned dst, const void* src) {
    asm volatile("cp.async.cg.shared.global [%0], [%1], 16;" :: "r"(dst), "l"(src) : "memory");
}

// ---- smem layout (floats) --------------------------------------------------
#define YS_OFF   0                        // y  [512][32] linear        16384
#define RS_OFF   16384                    // r  [32][516] padded        16512
#define XS_OFF   (RS_OFF + 16512)         // x  [32][36] padded          1152
#define YN2_OFF  (XS_OFF + 1152)          // |y|^2 [512]                  512
#define XN2_OFF  (YN2_OFF + 512)          // |x|^2 [32]                    32
#define PART_OFF (XN2_OFF + 32)           // warp partials [3][32][32]   3072
#define SMEM_FLOATS (PART_OFF + 3072)
#define SMEM_BYTES  (SMEM_FLOATS * 4)     // ~150 KB

// ---------------------------------------------------------------------------
// Single fused kernel, 32 Sinkhorn rows per block. lane = row, warp = m-chunk.
//  r (8MB stream): cp.async.cg, COALESCED, into padded smem; its latency is
//    hidden under the whole dot-product mainloop (wait + barrier after dots).
//  y,x: synchronous coalesced staging, |.|^2 via 8-lane shfl; one barrier.
//  dots: d-packed f32x2 FFMAs, y via broadcast LDS.128 (1 wf/instr), both
//    m-tiles computed before r is touched. C = sqrt(|x|^2+|y|^2-2dot);
//  K = exp2(-C*log2e/2); warp partials -> warp 0 scalar u-recurrence with
//  block-local early stop; out[n] = u*T/(u+1e-8).
// ---------------------------------------------------------------------------
__global__ __launch_bounds__(NT) void sinkhorn_fused_kernel(
    const float* __restrict__ x,   // [NN, DD]
    const float* __restrict__ y,   // [MM, DD]
    const float* __restrict__ r,   // [NN, MM]
    float* __restrict__ out)       // [NN]
{
    extern __shared__ float sm[];
    float4* ys4  = (float4*)(sm + YS_OFF);
    float4* rs4  = (float4*)(sm + RS_OFF);   // [32][129] float4 (516-f padded)
    float4* xs4  = (float4*)(sm + XS_OFF);
    float*  yn2  = sm + YN2_OFF;
    float*  xn2s = sm + XN2_OFF;
    float*  part = sm + PART_OFF;

    const int tid  = threadIdx.x;
    const int warp = tid >> 5;
    const int lane = tid & 31;
    const int nb   = blockIdx.x << 5;
    const int mc   = warp << 4;              // this warp's 16-column m-chunk

    // ---- r: cp.async.cg, coalesced (consecutive threads -> consecutive c4) -
    {
        const float4*  rg4 = (const float4*)r;
        const unsigned rs_base = (unsigned)__cvta_generic_to_shared(rs4);
#pragma unroll
        for (int k = 0; k < 4; k++) {
            int idx = tid + 1024 * k;
            int row = idx >> 7, c4 = idx & 127;
            cp_async16(rs_base + (unsigned)(row * 129 + c4) * 16u,
                       rg4 + (size_t)(nb + row) * 128 + c4);
        }
        asm volatile("cp.async.commit_group;" ::: "memory");
    }

    // ---- y staging: coalesced LDG.128, linear store + |y|^2 via shfl -------
    const float4* yg4 = (const float4*)y;    // 4096 float4
#pragma unroll
    for (int k = 0; k < 4; k++) {
        int idx  = tid + 1024 * k;
        float4 a = yg4[idx];
        ys4[idx] = a;
        float sq = fmaf(a.x, a.x, fmaf(a.y, a.y, fmaf(a.z, a.z, a.w * a.w)));
        sq += __shfl_xor_sync(0xffffffffu, sq, 1);
        sq += __shfl_xor_sync(0xffffffffu, sq, 2);
        sq += __shfl_xor_sync(0xffffffffu, sq, 4);
        if ((idx & 7) == 0) yn2[idx >> 3] = sq;
    }

    // ---- x staging (tid<256): padded copy + |x|^2 via shfl -----------------
    if (tid < 256) {
        int m = tid >> 3, slot = tid & 7;
        float4 a = ((const float4*)x)[(nb + m) * 8 + slot];
        xs4[m * 9 + slot] = a;
        float sq = fmaf(a.x, a.x, fmaf(a.y, a.y, fmaf(a.z, a.z, a.w * a.w)));
        sq += __shfl_xor_sync(0xffffffffu, sq, 1);
        sq += __shfl_xor_sync(0xffffffffu, sq, 2);
        sq += __shfl_xor_sync(0xffffffffu, sq, 4);
        if (slot == 0) xn2s[m] = sq;
    }
    __syncthreads();   // y, yn2, xs, xn2s visible (r still in flight)

    // ---- dots for BOTH m-tiles before touching r ---------------------------
    const ulonglong2* ys2 = (const ulonglong2*)ys4;   // [m][8] x 16B
    const ulonglong2* xs2 = (const ulonglong2*)xs4;   // [n][9] x 16B
    float dots[16];

#pragma unroll
    for (int mt = 0; mt < 2; mt++) {
        const int mb = mc + (mt << 3);       // m-tile of 8
        ull A[8] = {0, 0, 0, 0, 0, 0, 0, 0};
#pragma unroll
        for (int p2 = 0; p2 < 8; p2++) {     // 4 d's per step
            ulonglong2 xp = xs2[lane * 9 + p2];          // this row's x quad
#pragma unroll
            for (int j = 0; j < 8; j++) {
                ulonglong2 yp = ys2[(mb + j) * 8 + p2];  // broadcast LDS.128
                A[j] = ffma2(xp.x, yp.x, A[j]);
                A[j] = ffma2(xp.y, yp.y, A[j]);
            }
        }
#pragma unroll
        for (int j = 0; j < 8; j++)
            dots[8 * mt + j] = flo(A[j]) + fhi(A[j]);
    }

    // ---- r has had the whole mainloop to land ------------------------------
    asm volatile("cp.async.wait_group 0;" ::: "memory");
    __syncthreads();   // all threads' r tiles visible

    // ---- epilogue: 16 m-values per thread ----------------------------------
    const float xn2 = xn2s[lane];
    float Racc = 0.f, Sacc = 0.f, Tacc = 0.f;
#pragma unroll
    for (int mt = 0; mt < 2; mt++) {
        const int mb = mc + (mt << 3);
        float4 r4a = rs4[lane * 129 + (mc >> 2) + 2 * mt];
        float4 r4b = rs4[lane * 129 + (mc >> 2) + 2 * mt + 1];
        float rv[8] = { r4a.x, r4a.y, r4a.z, r4a.w, r4b.x, r4b.y, r4b.z, r4b.w };
#pragma unroll
        for (int j = 0; j < 8; j++) {
            float d2 = fmaf(-2.f, dots[8 * mt + j], xn2 + yn2[mb + j]);
            float C  = sqrt_approx(fmaxf(d2, 0.f));
            float K  = exp2f(C * -0.72134752f);          // exp(-C/2)
            Racc += K;
            float Kr = K * rv[j];
            Sacc += Kr;
            Tacc = fmaf(Kr, C, Tacc);
        }
    }

    // ---- combine 32 warp partials in fixed order (deterministic) -----------
    part[(0 * 32 + warp) * 32 + lane] = Racc;
    part[(1 * 32 + warp) * 32 + lane] = Sacc;
    part[(2 * 32 + warp) * 32 + lane] = Tacc;
    __syncthreads();

    if (warp == 0) {
        float R = 0.f, S = 0.f, T = 0.f;
#pragma unroll
        for (int w = 0; w < 32; w++) {
            R += part[(0 * 32 + w) * 32 + lane];
            S += part[(1 * 32 + w) * 32 + lane];
            T += part[(2 * 32 + w) * 32 + lane];
        }

        // Scalar Sinkhorn recurrence, block-local early stop:
        //   iter 1:   u = 1/(R + 1e-8)
        //   iter t>1: u = 1/(S/(u+1e-8) + 1e-8)
        //   stop once mean_32 |u_new - u| < 0.1 (after applying update)
        float u = 1.f;
        bool done = false;
        for (int t = 0; t < 100 && !done; t++) {
            float denom = (t == 0) ? R : (S / (u + 1e-8f));
            float un = 1.f / (denom + 1e-8f);
            float e = fabsf(un - u);
            u = un;
#pragma unroll
            for (int off = 16; off > 0; off >>= 1)
                e += __shfl_xor_sync(0xffffffffu, e, off);
            done = (e < 0.1f * 32.f);        // uniform across warp
        }
        out[nb + lane] = u * T / (u + 1e-8f);
    }
}

extern "C" void kernel_launch(void* const* d_in, const int* in_sizes, int n_in,
                              void* d_out, int out_size)
{
    const float* x = (const float*)d_in[0];  // [4096, 32]
    const float* y = (const float*)d_in[1];  // [512, 32]
    const float* r = (const float*)d_in[2];  // [4096, 512]
    float* out = (float*)d_out;              // [4096]

    cudaFuncSetAttribute(sinkhorn_fused_kernel,
                         cudaFuncAttributeMaxDynamicSharedMemorySize, SMEM_BYTES);
    sinkhorn_fused_kernel<<<NBLK, NT, SMEM_BYTES>>>(x, y, r, out);
}